// round 2
// baseline (speedup 1.0000x reference)
#include <cuda_runtime.h>
#include <math.h>

// Problem constants
#define NROWS (32*64*64)          // 131072 rows of dim 64
#define D 64
#define KCODES 512
#define THREADS 256
#define NBLOCKS (NROWS/THREADS)   // 512
#define KC 32                     // codes per k-chunk
#define NCHUNK (KCODES/KC)        // 16

#define OUT_ELEMS ((size_t)NROWS*(size_t)D)      // 8388608
#define DIFF_OFF  (OUT_ELEMS)                    // scalar diff
#define IND_OFF   (OUT_ELEMS + 1)                // 131072 indices (as f32)
#define PPL_OFF   (OUT_ELEMS + 1 + (size_t)NROWS)// scalar perplexity

// Scratch (no cudaMalloc allowed)
__device__ float g_en[KCODES];          // ||e_k||^2  (reference rounding order)
__device__ float g_eT[KCODES*D];        // transposed codebook [K][D]
__device__ float g_partial[NBLOCKS];    // per-block diff partial sums

// ---------------------------------------------------------------------------
// Prep: codebook column norms + transpose. embed is [D, K] row-major.
// Norm must match XLA: sequential over d, separate mul/add roundings (no FMA).
// ---------------------------------------------------------------------------
__global__ void vq_prep(const float* __restrict__ embed) {
    int k = threadIdx.x;   // 512 threads, one per code
    float s = 0.f;
#pragma unroll
    for (int d = 0; d < D; d++) {
        float v = embed[d*KCODES + k];   // coalesced across k
        s = __fadd_rn(s, __fmul_rn(v, v));
        g_eT[k*D + d] = v;
    }
    g_en[k] = s;
}

// ---------------------------------------------------------------------------
// Main: one row per thread. Stream codebook through SMEM in chunks of KC
// codes; accumulate dot products with packed f32x2 FMAs (per-lane IEEE fma,
// sequential in d == Eigen gebp accumulation order). Distance replicates the
// reference rounding chain exactly:
//     dist = fl( fl( fnorm - 2*dot ) + enorm )
// so ties quantized at ulp(~64) resolve identically (first-index argmin).
// ---------------------------------------------------------------------------
__global__ void __launch_bounds__(THREADS, 2)
vq_main(const float* __restrict__ x, const float* __restrict__ embed,
        float* __restrict__ dout) {
    __shared__ float es[D*KC];      // 8 KB codebook chunk, [d][k] layout
    __shared__ float ens[KCODES];   // 2 KB code norms
    __shared__ float red[THREADS];  // 1 KB reduction buffer

    const int tid = threadIdx.x;
    const size_t row = (size_t)blockIdx.x * THREADS + tid;

    for (int i = tid; i < KCODES; i += THREADS) ens[i] = g_en[i];

    // Row vector into registers (fully unrolled -> stays in regs)
    float f[D];
    {
        const float4* xp = (const float4*)(x + row * D);
#pragma unroll
        for (int i = 0; i < D/4; i++) {
            float4 v = xp[i];
            f[4*i+0] = v.x; f[4*i+1] = v.y; f[4*i+2] = v.z; f[4*i+3] = v.w;
        }
    }

    // ||f||^2 with XLA rounding order: sequential, mul then add, NO fma.
    float fn = 0.f;
#pragma unroll
    for (int i = 0; i < D; i++) fn = __fadd_rn(fn, __fmul_rn(f[i], f[i]));

    float best = 3.4e38f;
    int bestk = 0;

    for (int c = 0; c < NCHUNK; c++) {
        __syncthreads();   // previous chunk fully consumed
        // load chunk: es[d*KC + kk] = embed[d*K + c*KC + kk], vectorized
        for (int i = tid; i < D*KC/4; i += THREADS) {
            int d  = i / (KC/4);
            int kq = i % (KC/4);
            ((float4*)es)[i] =
                __ldg((const float4*)(embed + d*KCODES + c*KC) + kq);
        }
        __syncthreads();   // chunk visible

        // 16 packed accumulators = 32 scalar dots
        unsigned long long acc[KC/2];
#pragma unroll
        for (int j = 0; j < KC/2; j++) acc[j] = 0ull;

#pragma unroll
        for (int d = 0; d < D; d++) {
            unsigned long long fd2;
            asm("mov.b64 %0, {%1, %1};" : "=l"(fd2) : "f"(f[d]));
            const ulonglong2* e4 = (const ulonglong2*)(es + d*KC);
#pragma unroll
            for (int j = 0; j < KC/4; j++) {
                ulonglong2 ev = e4[j];  // LDS.128, warp-broadcast
                asm("fma.rn.f32x2 %0, %1, %2, %0;"
                    : "+l"(acc[2*j])   : "l"(fd2), "l"(ev.x));
                asm("fma.rn.f32x2 %0, %1, %2, %0;"
                    : "+l"(acc[2*j+1]) : "l"(fd2), "l"(ev.y));
            }
        }

        // dist = fl( fl(fn - 2*dot) + ||e||^2 )  -- reference op order
#pragma unroll
        for (int j = 0; j < KC/2; j++) {
            float lo, hi;
            asm("mov.b64 {%0, %1}, %2;" : "=f"(lo), "=f"(hi) : "l"(acc[j]));
            int k0 = c*KC + 2*j;
            float d0 = __fadd_rn(__fsub_rn(fn, __fadd_rn(lo, lo)), ens[k0]);
            float d1 = __fadd_rn(__fsub_rn(fn, __fadd_rn(hi, hi)), ens[k0+1]);
            if (d0 < best) { best = d0; bestk = k0;   }
            if (d1 < best) { best = d1; bestk = k0+1; }
        }
    }

    // Epilogue: gather quantized code, write out, accumulate MSE
    float ds = 0.f;
    {
        const float4* q4 = (const float4*)(g_eT + (size_t)bestk * D);
        float4* o4 = (float4*)(dout + row * D);
#pragma unroll
        for (int i = 0; i < D/4; i++) {
            float4 q = q4[i];
            o4[i] = q;
            float a = q.x - f[4*i+0];
            float b = q.y - f[4*i+1];
            float cc = q.z - f[4*i+2];
            float dd = q.w - f[4*i+3];
            ds += a*a + b*b + cc*cc + dd*dd;
        }
    }
    dout[IND_OFF + row] = (float)bestk;

    // deterministic block tree-reduce of diff partials
    red[tid] = ds;
    __syncthreads();
#pragma unroll
    for (int s = THREADS/2; s > 0; s >>= 1) {
        if (tid < s) red[tid] += red[tid + s];
        __syncthreads();
    }
    if (tid == 0) g_partial[blockIdx.x] = red[0];
}

// ---------------------------------------------------------------------------
// Finalize: deterministic double-precision reduce of partials -> diff,
// plus the (data-independent) perplexity constant.
// ---------------------------------------------------------------------------
__global__ void vq_fin(float* __restrict__ dout) {
    __shared__ double rd[NBLOCKS];
    int t = threadIdx.x;
    rd[t] = (double)g_partial[t];
    __syncthreads();
#pragma unroll
    for (int s = NBLOCKS/2; s > 0; s >>= 1) {
        if (t < s) rd[t] += rd[t + s];
        __syncthreads();
    }
    if (t == 0) {
        dout[DIFF_OFF] = (float)(rd[0] / (double)OUT_ELEMS);
        // p = mean(one_hot) over ALL N*K entries = exactly 1/512 (data-free)
        float p = 1.0f / 512.0f;
        dout[PPL_OFF] = expf(-(p * logf(p + 1e-10f)));
    }
}

// ---------------------------------------------------------------------------
extern "C" void kernel_launch(void* const* d_in, const int* in_sizes, int n_in,
                              void* d_out, int out_size) {
    const float* x     = (const float*)d_in[0];   // [32,64,64,64] f32
    const float* embed = (const float*)d_in[1];   // [1,1,64,512]  f32
    float* dout = (float*)d_out;

    vq_prep<<<1, KCODES>>>(embed);
    vq_main<<<NBLOCKS, THREADS>>>(x, embed, dout);
    vq_fin<<<1, NBLOCKS>>>(dout);
}

// round 3
// speedup vs baseline: 1.0562x; 1.0562x over previous
#include <cuda_runtime.h>
#include <math.h>

// Problem constants
#define NROWS (32*64*64)          // 131072 rows of dim 64
#define D 64
#define KCODES 512
#define THREADS 256
#define NBLOCKS (NROWS/THREADS)   // 512
#define KC 16                     // codes per k-chunk (16 -> 8 packed accs)
#define NCHUNK (KCODES/KC)        // 32

#define OUT_ELEMS ((size_t)NROWS*(size_t)D)      // 8388608
#define DIFF_OFF  (OUT_ELEMS)                    // scalar diff
#define IND_OFF   (OUT_ELEMS + 1)                // 131072 indices (as f32)
#define PPL_OFF   (OUT_ELEMS + 1 + (size_t)NROWS)// scalar perplexity

// Scratch (no cudaMalloc allowed)
__device__ float g_en[KCODES];          // ||e_k||^2  (reference rounding order)
__device__ float g_eT[KCODES*D];        // transposed codebook [K][D]
__device__ float g_partial[NBLOCKS];    // per-block diff partial sums

// ---------------------------------------------------------------------------
// Prep (parallel): 4 blocks x 256 threads, each block owns 128 codes.
// Coalesced global reads into an smem tile, then transpose-out + norms.
// Norm rounding matches XLA: sequential over d, separate mul/add (no FMA).
// ---------------------------------------------------------------------------
#define PK 128   // codes per prep block
__global__ void vq_prep(const float* __restrict__ embed) {
    __shared__ float tile[D * PK];   // 32 KB: tile[d*PK + kl]
    const int tid = threadIdx.x;
    const int k0  = blockIdx.x * PK;

    // Coalesced load: 64*128 floats = 2048 float4, 8 per thread
    for (int i = tid; i < D * PK / 4; i += THREADS) {
        int d  = i / (PK/4);
        int kq = i % (PK/4);
        ((float4*)tile)[i] =
            __ldg((const float4*)(embed + d*KCODES + k0) + kq);
    }
    __syncthreads();

    // Transpose out: i -> (dq = i/PK, kl = i%PK); smem reads conflict-free.
    for (int i = tid; i < (D/4) * PK; i += THREADS) {
        int dq = i / PK;
        int kl = i % PK;
        float4 v;
        v.x = tile[(4*dq+0)*PK + kl];
        v.y = tile[(4*dq+1)*PK + kl];
        v.z = tile[(4*dq+2)*PK + kl];
        v.w = tile[(4*dq+3)*PK + kl];
        *(float4*)(g_eT + (size_t)(k0 + kl)*D + 4*dq) = v;
    }

    // Norms: first 128 threads, one code each, sequential d, no FMA.
    if (tid < PK) {
        float s = 0.f;
#pragma unroll
        for (int d = 0; d < D; d++) {
            float v = tile[d*PK + tid];
            s = __fadd_rn(s, __fmul_rn(v, v));
        }
        g_en[k0 + tid] = s;
    }
}

// ---------------------------------------------------------------------------
// Main: one row per thread. Codebook streamed through double-buffered SMEM
// in chunks of KC=16 codes (8 packed f32x2 accumulators -> low reg pressure,
// no spills at occupancy 2). Dot accumulation is sequential in d per output
// element (== Eigen gebp order); distance replicates the reference rounding
// chain exactly:  dist = fl( fl(fnorm - 2*dot) + enorm ).
// ---------------------------------------------------------------------------
__global__ void __launch_bounds__(THREADS, 2)
vq_main(const float* __restrict__ x, const float* __restrict__ embed,
        float* __restrict__ dout) {
    __shared__ float es[2][D*KC];   // 2 x 4 KB chunk buffers, [d][k] layout
    __shared__ float ens[KCODES];   // 2 KB code norms
    __shared__ float red[THREADS];  // 1 KB reduction buffer

    const int tid = threadIdx.x;
    const size_t row = (size_t)blockIdx.x * THREADS + tid;

    for (int i = tid; i < KCODES; i += THREADS) ens[i] = g_en[i];

    // Per-thread chunk-load slot: one float4 per chunk.
    // float4 index within chunk c: d*(K/4) + c*(KC/4) + kq  with d=tid/4, kq=tid&3
    const int ld_d = tid >> 2;
    const int ld_k = tid & 3;
    const float4* ebase = (const float4*)embed + ld_d*(KCODES/4) + ld_k;

    // Row vector into registers
    float f[D];
    {
        const float4* xp = (const float4*)(x + row * D);
#pragma unroll
        for (int i = 0; i < D/4; i++) {
            float4 v = xp[i];
            f[4*i+0] = v.x; f[4*i+1] = v.y; f[4*i+2] = v.z; f[4*i+3] = v.w;
        }
    }

    // ||f||^2 with XLA rounding order: sequential, mul then add, NO fma.
    float fn = 0.f;
#pragma unroll
    for (int i = 0; i < D; i++) fn = __fadd_rn(fn, __fmul_rn(f[i], f[i]));

    // Pipeline prologue: chunk 0 into buffer 0; prefetch chunk 1 into regs.
    ((float4*)es[0])[tid] = __ldg(ebase + 0*(KC/4));
    __syncthreads();
    float4 pref = __ldg(ebase + 1*(KC/4));

    float best = 3.4e38f;
    int bestk = 0;

    for (int c = 0; c < NCHUNK; c++) {
        const float* eb = es[c & 1];

        // 8 packed accumulators = 16 scalar dots
        unsigned long long acc[KC/2];
#pragma unroll
        for (int j = 0; j < KC/2; j++) acc[j] = 0ull;

#pragma unroll
        for (int d = 0; d < D; d++) {
            unsigned long long fd2;
            asm("mov.b64 %0, {%1, %1};" : "=l"(fd2) : "f"(f[d]));
            const ulonglong2* e4 = (const ulonglong2*)(eb + d*KC);
#pragma unroll
            for (int j = 0; j < KC/4; j++) {
                ulonglong2 ev = e4[j];  // LDS.128 broadcast
                asm("fma.rn.f32x2 %0, %1, %2, %0;"
                    : "+l"(acc[2*j])   : "l"(fd2), "l"(ev.x));
                asm("fma.rn.f32x2 %0, %1, %2, %0;"
                    : "+l"(acc[2*j+1]) : "l"(fd2), "l"(ev.y));
            }
        }

        // dist = fl( fl(fn - 2*dot) + ||e||^2 )  -- reference op order
#pragma unroll
        for (int j = 0; j < KC/2; j++) {
            float lo, hi;
            asm("mov.b64 {%0, %1}, %2;" : "=f"(lo), "=f"(hi) : "l"(acc[j]));
            int k0 = c*KC + 2*j;
            float d0 = __fadd_rn(__fsub_rn(fn, __fadd_rn(lo, lo)), ens[k0]);
            float d1 = __fadd_rn(__fsub_rn(fn, __fadd_rn(hi, hi)), ens[k0+1]);
            if (d0 < best) { best = d0; bestk = k0;   }
            if (d1 < best) { best = d1; bestk = k0+1; }
        }

        // Stage next chunk (buffer consumed two iterations ago -> safe),
        // then one sync, then prefetch chunk c+2 from L2.
        if (c + 1 < NCHUNK)
            ((float4*)es[(c+1) & 1])[tid] = pref;
        __syncthreads();
        if (c + 2 < NCHUNK)
            pref = __ldg(ebase + (c+2)*(KC/4));
    }

    // Epilogue: gather quantized code, write out, accumulate MSE
    float ds = 0.f;
    {
        const float4* q4 = (const float4*)(g_eT + (size_t)bestk * D);
        float4* o4 = (float4*)(dout + row * D);
#pragma unroll
        for (int i = 0; i < D/4; i++) {
            float4 q = q4[i];
            o4[i] = q;
            float a = q.x - f[4*i+0];
            float b = q.y - f[4*i+1];
            float cc = q.z - f[4*i+2];
            float dd = q.w - f[4*i+3];
            ds += a*a + b*b + cc*cc + dd*dd;
        }
    }
    dout[IND_OFF + row] = (float)bestk;

    // deterministic block tree-reduce of diff partials
    red[tid] = ds;
    __syncthreads();
#pragma unroll
    for (int s = THREADS/2; s > 0; s >>= 1) {
        if (tid < s) red[tid] += red[tid + s];
        __syncthreads();
    }
    if (tid == 0) g_partial[blockIdx.x] = red[0];
}

// ---------------------------------------------------------------------------
// Finalize: deterministic double-precision reduce of partials -> diff,
// plus the (data-independent) perplexity constant.
// ---------------------------------------------------------------------------
__global__ void vq_fin(float* __restrict__ dout) {
    __shared__ double rd[NBLOCKS];
    int t = threadIdx.x;
    rd[t] = (double)g_partial[t];
    __syncthreads();
#pragma unroll
    for (int s = NBLOCKS/2; s > 0; s >>= 1) {
        if (t < s) rd[t] += rd[t + s];
        __syncthreads();
    }
    if (t == 0) {
        dout[DIFF_OFF] = (float)(rd[0] / (double)OUT_ELEMS);
        // p = mean(one_hot) over ALL N*K entries = exactly 1/512 (data-free)
        float p = 1.0f / 512.0f;
        dout[PPL_OFF] = expf(-(p * logf(p + 1e-10f)));
    }
}

// ---------------------------------------------------------------------------
extern "C" void kernel_launch(void* const* d_in, const int* in_sizes, int n_in,
                              void* d_out, int out_size) {
    const float* x     = (const float*)d_in[0];   // [32,64,64,64] f32
    const float* embed = (const float*)d_in[1];   // [1,1,64,512]  f32
    float* dout = (float*)d_out;

    vq_prep<<<KCODES/PK, THREADS>>>(embed);
    vq_main<<<NBLOCKS, THREADS>>>(x, embed, dout);
    vq_fin<<<1, NBLOCKS>>>(dout);
}